// round 4
// baseline (speedup 1.0000x reference)
#include <cuda_runtime.h>
#include <cstdint>

// ---------------------------------------------------------------------------
// MambaBlock: B=2, T=1024, DM=1024, D=2048, N=16, K=4, DTR=128
// Round 4: tf32 mma GEMMs with pre-rounded, k-permuted operands (no cvt /
// scalar LDS in hot loop), LDS.64 fragments, split-K dbc.
// k-perm within 8: p(k) = (k&~7) | ((k&3)<<1) | ((k>>2)&1)
// ---------------------------------------------------------------------------

#define DMv   1024
#define Dv    2048
#define Tv    1024
#define NROWS 2048     // B*T
#define NSTv  16

// Scratch layout (floats)
#define OFF_H      0u          // 2048*1024   (rounded, k-perm)
#define OFF_PROJ   2097152u    // 2048*4096   (plain)
#define OFF_X1C    10485760u   // 2048*2048   (plain, for scan)
#define OFF_DBC    14680064u   // 2048*160    (delta cols rounded+perm; B/C plain)
#define OFF_DELTA  15007744u   // 2048*2048   (plain)
#define OFF_YMOD   19202048u   // 2048*2048   (rounded, k-perm)
#define OFF_DBCP   23396352u   // 4*2048*160  split-K partials
#define OFF_X1CP   24707072u   // 2048*2048   (rounded, k-perm, for dbc GEMM)
#define OFF_WIN    28901376u   // 4096*1024   in_W^T  perm
#define OFF_WDBC   33095680u   // 192*2048    dbc_W^T perm (padded rows)
#define OFF_WDUP   33488896u   // 2048*128    dup_W^T perm
#define OFF_WOUT   33751040u   // 1024*2048   out_W^T perm
#define SCRATCH_FLOATS 35848192u

__device__ __align__(128) float g_scratch[SCRATCH_FLOATS];

__device__ __forceinline__ float silu_f(float v) {
    return v * (1.0f / (1.0f + __expf(-v)));
}

__device__ __forceinline__ float tf32r(float f) {
    unsigned u;
    asm("cvt.rna.tf32.f32 %0, %1;" : "=r"(u) : "f"(f));
    return __uint_as_float(u);
}

__device__ __forceinline__ int pkf(int k) {
    return (k & ~7) | ((k & 3) << 1) | ((k >> 2) & 1);
}

__device__ __forceinline__ void cp16(float* dst, const float* src, bool p) {
    unsigned d = (unsigned)__cvta_generic_to_shared(dst);
    int sz = p ? 16 : 0;
    asm volatile("cp.async.cg.shared.global [%0], [%1], 16, %2;\n"
                 :: "r"(d), "l"(src), "r"(sz));
}

// ---------------------------------------------------------------------------
// Weight transform: W[K][N] -> Wt[N][K], tf32-rounded, k permuted within 8.
// All dims multiples of 32. Grid (K/32, N/32), 256 threads.
// ---------------------------------------------------------------------------
__global__ void __launch_bounds__(256) wtrans_k(
    const float* __restrict__ W, float* __restrict__ Wt, int K, int N)
{
    __shared__ float t[32][33];
    int k0 = blockIdx.x * 32, n0 = blockIdx.y * 32;
    int tx = threadIdx.x & 31, ty0 = threadIdx.x >> 5;
    #pragma unroll
    for (int j = 0; j < 4; j++) {
        int ty = ty0 + j * 8;
        t[ty][tx] = W[(size_t)(k0 + ty) * N + n0 + tx];
    }
    __syncthreads();
    int pk = pkf(tx);
    #pragma unroll
    for (int j = 0; j < 4; j++) {
        int ty = ty0 + j * 8;
        Wt[(size_t)(n0 + ty) * K + k0 + pk] = tf32r(t[tx][ty]);
    }
}

// ---------------------------------------------------------------------------
// RMSNorm -> h (tf32-rounded, k-permuted columns)
// ---------------------------------------------------------------------------
__global__ void __launch_bounds__(256) rmsnorm_k(
    const float* __restrict__ x, const float* __restrict__ w, float* __restrict__ out)
{
    int row = blockIdx.x;
    const float4* xr = reinterpret_cast<const float4*>(x + (size_t)row * DMv);
    float4 v = xr[threadIdx.x];
    float s = v.x * v.x + v.y * v.y + v.z * v.z + v.w * v.w;
    #pragma unroll
    for (int o = 16; o; o >>= 1) s += __shfl_xor_sync(0xffffffffu, s, o);
    __shared__ float ws[8];
    if ((threadIdx.x & 31) == 0) ws[threadIdx.x >> 5] = s;
    __syncthreads();
    float tot = 0.f;
    #pragma unroll
    for (int i = 0; i < 8; i++) tot += ws[i];
    float scale = rsqrtf(tot * (1.0f / (float)DMv) + 1e-6f);
    float4 wv = reinterpret_cast<const float4*>(w)[threadIdx.x];
    float o4[4] = { v.x * scale * wv.x, v.y * scale * wv.y,
                    v.z * scale * wv.z, v.w * scale * wv.w };
    float* orow = out + (size_t)row * DMv;
    int c0 = threadIdx.x * 4;
    #pragma unroll
    for (int j = 0; j < 4; j++) orow[pkf(c0 + j)] = tf32r(o4[j]);
}

// ---------------------------------------------------------------------------
// Pipelined tf32 tensor-core GEMM, operands pre-rounded & k-permuted.
// A[M][lda] row-major (perm-k), Bt[N][ldb] row-major (perm-k).
// BM=128, BK=32, BN in {64,128}. 256 thr = 8 warps 4(M)x2(N).
// EPI 0: +bias  1: +bias,softplus  2: +bias,+res  3: raw (split-K partial)
// blockIdx.z = split-K part (offsets A/Bt cols by part*Kd, C by part*partStride)
// ---------------------------------------------------------------------------
template <int BN, int EPI>
__global__ void __launch_bounds__(256, 2) gemm_tc(
    const float* __restrict__ A, const float* __restrict__ Bt,
    const float* __restrict__ bias, float* __restrict__ C,
    int N, int Kd, int lda, int ldb, const float* __restrict__ res, size_t partStride)
{
    constexpr int BM = 128, BK = 32, STR = BK + 8;  // 40
    constexpr int WNT = BN / 16;
    constexpr int NBI = BN / 32;     // B 16B-chunks per thread
    constexpr int ASZ = BM * STR, BSZ = BN * STR, STAGE = ASZ + BSZ;

    extern __shared__ float smem[];

    int tid = threadIdx.x, lane = tid & 31, warp = tid >> 5;
    int wm = warp >> 1, wn = warp & 1;
    int bm = blockIdx.y * BM, bn = blockIdx.x * BN;
    int part = blockIdx.z;
    const float* Ap = A + (size_t)part * Kd;
    const float* Bp = Bt + (size_t)part * Kd;
    float* Cp = C + (size_t)part * partStride;

    float acc[2][WNT][4];
    #pragma unroll
    for (int i = 0; i < 2; i++)
        #pragma unroll
        for (int j = 0; j < WNT; j++)
            #pragma unroll
            for (int q = 0; q < 4; q++) acc[i][j][q] = 0.f;

    auto issue = [&](int st, int kt) {
        float* As = smem + st * STAGE;
        float* Bs = As + ASZ;
        #pragma unroll
        for (int i = 0; i < 4; i++) {
            int li = tid + i * 256;
            int m = li >> 3, c = (li & 7) * 4;
            cp16(As + m * STR + c, Ap + (size_t)(bm + m) * lda + kt + c, true);
        }
        #pragma unroll
        for (int i = 0; i < NBI; i++) {
            int li = tid + i * 256;
            int n = li >> 3, c = (li & 7) * 4;
            cp16(Bs + n * STR + c, Bp + (size_t)(bn + n) * ldb + kt + c, (bn + n) < N);
        }
        asm volatile("cp.async.commit_group;\n" ::: "memory");
    };

    auto compute = [&](int st) {
        const float* As = smem + st * STAGE;
        const float* Bs = As + ASZ;
        #pragma unroll
        for (int ks = 0; ks < BK / 8; ks++) {
            int off = ks * 8 + 2 * (lane & 3);
            uint2 alo[2], ahi[2];
            #pragma unroll
            for (int mi = 0; mi < 2; mi++) {
                int mr = wm * 32 + mi * 16 + (lane >> 2);
                alo[mi] = *reinterpret_cast<const uint2*>(As + mr * STR + off);
                ahi[mi] = *reinterpret_cast<const uint2*>(As + (mr + 8) * STR + off);
            }
            #pragma unroll
            for (int ni = 0; ni < WNT; ni++) {
                int nc = wn * (BN / 2) + ni * 8 + (lane >> 2);
                uint2 b = *reinterpret_cast<const uint2*>(Bs + nc * STR + off);
                #pragma unroll
                for (int mi = 0; mi < 2; mi++) {
                    asm volatile(
                        "mma.sync.aligned.m16n8k8.row.col.f32.tf32.tf32.f32 "
                        "{%0,%1,%2,%3}, {%4,%5,%6,%7}, {%8,%9}, {%0,%1,%2,%3};\n"
                        : "+f"(acc[mi][ni][0]), "+f"(acc[mi][ni][1]),
                          "+f"(acc[mi][ni][2]), "+f"(acc[mi][ni][3])
                        : "r"(alo[mi].x), "r"(ahi[mi].x), "r"(alo[mi].y), "r"(ahi[mi].y),
                          "r"(b.x), "r"(b.y));
                }
            }
        }
    };

    int nt = Kd / BK;
    issue(0, 0);
    int s = 0;
    for (int i = 0; i < nt; i++) {
        asm volatile("cp.async.wait_group 0;\n" ::: "memory");
        __syncthreads();
        if (i + 1 < nt) issue(s ^ 1, (i + 1) * BK);
        compute(s);
        s ^= 1;
        if (i + 1 < nt) __syncthreads();
    }

    // Epilogue (float2 stores; N even)
    #pragma unroll
    for (int mi = 0; mi < 2; mi++) {
        int r0 = bm + wm * 32 + mi * 16 + (lane >> 2);
        #pragma unroll
        for (int ni = 0; ni < WNT; ni++) {
            int c0 = bn + wn * (BN / 2) + ni * 8 + (lane & 3) * 2;
            if (c0 >= N) continue;
            #pragma unroll
            for (int h = 0; h < 2; h++) {
                int rr = r0 + h * 8;
                float v0 = acc[mi][ni][h * 2 + 0];
                float v1 = acc[mi][ni][h * 2 + 1];
                if (EPI != 3) { v0 += bias[c0]; v1 += bias[c0 + 1]; }
                if (EPI == 1) {
                    v0 = (v0 > 20.0f) ? v0 : log1pf(__expf(v0));
                    v1 = (v1 > 20.0f) ? v1 : log1pf(__expf(v1));
                }
                if (EPI == 2) {
                    float2 rv = *reinterpret_cast<const float2*>(&res[(size_t)rr * N + c0]);
                    v0 += rv.x; v1 += rv.y;
                }
                *reinterpret_cast<float2*>(&Cp[(size_t)rr * N + c0]) = make_float2(v0, v1);
            }
        }
    }
}

// ---------------------------------------------------------------------------
// Split-K reduce: dbc = sum of 4 partials + bias.
// delta cols (0..127): tf32-rounded + k-permuted (feeds gemm3 A).
// B/C cols (128..159): plain (feed scan).
// ---------------------------------------------------------------------------
__global__ void __launch_bounds__(256) reduce4_k(
    const float* __restrict__ P, const float* __restrict__ bias, float* __restrict__ C)
{
    const size_t PS = (size_t)NROWS * 160;
    size_t i = (size_t)blockIdx.x * 256 + threadIdx.x;
    int col = (int)(i % 160);
    size_t row = i / 160;
    float v = P[i] + P[i + PS] + P[i + 2 * PS] + P[i + 3 * PS] + bias[col];
    if (col < 128) C[row * 160 + pkf(col)] = tf32r(v);
    else           C[i] = v;
}

// ---------------------------------------------------------------------------
// Depthwise causal conv (K=4) + SiLU.
// Writes x1c (plain, for scan) and x1cp (rounded + k-perm, for dbc GEMM).
// ---------------------------------------------------------------------------
__global__ void __launch_bounds__(256) conv_silu_k(
    const float* __restrict__ proj, const float* __restrict__ cw,
    const float* __restrict__ cb, float* __restrict__ out, float* __restrict__ outp)
{
    int d = blockIdx.x * 256 + threadIdx.x;
    int row = blockIdx.y;
    int t = row & (Tv - 1);
    int b = row >> 10;
    float4 w = *reinterpret_cast<const float4*>(cw + (size_t)d * 4);
    float acc = cb[d];
    const float* base = proj + (size_t)(b * Tv) * 4096 + d;
    if (t >= 3) acc = fmaf(base[(size_t)(t - 3) * 4096], w.x, acc);
    if (t >= 2) acc = fmaf(base[(size_t)(t - 2) * 4096], w.y, acc);
    if (t >= 1) acc = fmaf(base[(size_t)(t - 1) * 4096], w.z, acc);
    acc = fmaf(base[(size_t)t * 4096], w.w, acc);
    float sv = silu_f(acc);
    out[(size_t)row * Dv + d] = sv;
    outp[(size_t)row * Dv + pkf(d)] = tf32r(sv);
}

// ---------------------------------------------------------------------------
// Selective scan. 256 thr = 16 channels x 16 states. Writes ymod rounded+perm.
// ---------------------------------------------------------------------------
__global__ void __launch_bounds__(256) scan_k(
    const float* __restrict__ dbc, const float* __restrict__ delta,
    const float* __restrict__ x1c, const float* __restrict__ proj,
    const float* __restrict__ A_log, float* __restrict__ ymod)
{
    __shared__ float Bs[128][16];
    __shared__ float Cs[128][16];
    __shared__ float Ys[128][16];
    int tid = threadIdx.x;
    int n = tid & 15, grp = tid >> 4;
    int b = blockIdx.y;
    int d = blockIdx.x * 16 + grp;
    float An = -__expf(A_log[(size_t)d * NSTv + n]);
    float h = 0.f;

    for (int c = 0; c < 8; c++) {
        __syncthreads();
        int t0 = c * 128;
        for (int idx = tid; idx < 2048; idx += 256) {
            int tl = idx >> 4, nn = idx & 15;
            size_t r = (size_t)(b * Tv + t0 + tl) * 160;
            Bs[tl][nn] = dbc[r + 128 + nn];
            Cs[tl][nn] = dbc[r + 144 + nn];
        }
        __syncthreads();
        const float* dl = delta + (size_t)(b * Tv + t0) * Dv + d;
        const float* xv = x1c  + (size_t)(b * Tv + t0) * Dv + d;
        #pragma unroll 4
        for (int tl = 0; tl < 128; tl++) {
            float de = dl[(size_t)tl * Dv];
            float xx = xv[(size_t)tl * Dv];
            float a = __expf(de * An);
            h = fmaf(a, h, de * Bs[tl][n] * xx);
            float p = h * Cs[tl][n];
            p += __shfl_xor_sync(0xffffffffu, p, 8);
            p += __shfl_xor_sync(0xffffffffu, p, 4);
            p += __shfl_xor_sync(0xffffffffu, p, 2);
            p += __shfl_xor_sync(0xffffffffu, p, 1);
            if (n == 0) Ys[tl][grp] = p;
        }
        __syncthreads();
        for (int idx = tid; idx < 2048; idx += 256) {
            int tl = idx >> 4, dl2 = idx & 15;
            int row = b * Tv + t0 + tl;
            int dd = blockIdx.x * 16 + dl2;
            float g = proj[(size_t)row * 4096 + 2048 + dd];
            ymod[(size_t)row * Dv + pkf(dd)] = tf32r(Ys[tl][dl2] * silu_f(g));
        }
    }
}

// ---------------------------------------------------------------------------
extern "C" void kernel_launch(void* const* d_in, const int* in_sizes, int n_in,
                              void* d_out, int out_size)
{
    const float* x      = (const float*)d_in[0];
    const float* rms_w  = (const float*)d_in[1];
    const float* in_W   = (const float*)d_in[2];
    const float* in_b   = (const float*)d_in[3];
    const float* conv_w = (const float*)d_in[4];
    const float* conv_b = (const float*)d_in[5];
    const float* A_log  = (const float*)d_in[6];
    const float* dbc_W  = (const float*)d_in[7];
    const float* dbc_b  = (const float*)d_in[8];
    const float* dup_W  = (const float*)d_in[9];
    const float* dup_b  = (const float*)d_in[10];
    const float* out_W  = (const float*)d_in[11];
    const float* out_b  = (const float*)d_in[12];
    float* out = (float*)d_out;

    float* S = nullptr;
    cudaGetSymbolAddress((void**)&S, g_scratch);

    const int SM128 = 2 * (128 * 40 + 128 * 40) * 4;   // 81920 B
    const int SM64  = 2 * (128 * 40 + 64 * 40) * 4;    // 61440 B
    cudaFuncSetAttribute(gemm_tc<128, 0>, cudaFuncAttributeMaxDynamicSharedMemorySize, SM128);
    cudaFuncSetAttribute(gemm_tc<128, 1>, cudaFuncAttributeMaxDynamicSharedMemorySize, SM128);
    cudaFuncSetAttribute(gemm_tc<64, 2>,  cudaFuncAttributeMaxDynamicSharedMemorySize, SM64);
    cudaFuncSetAttribute(gemm_tc<64, 3>,  cudaFuncAttributeMaxDynamicSharedMemorySize, SM64);

    // 0. Weight transforms (rounded, transposed, k-permuted)
    wtrans_k<<<dim3(32, 128), 256>>>(in_W,  S + OFF_WIN,  1024, 4096);
    wtrans_k<<<dim3(64, 5),   256>>>(dbc_W, S + OFF_WDBC, 2048, 160);
    wtrans_k<<<dim3(4, 64),   256>>>(dup_W, S + OFF_WDUP, 128,  2048);
    wtrans_k<<<dim3(64, 32),  256>>>(out_W, S + OFF_WOUT, 2048, 1024);

    // 1. RMSNorm -> h (rounded, perm)
    rmsnorm_k<<<NROWS, 256>>>(x, rms_w, S + OFF_H);

    // 2. in_proj: (2048x1024)@(1024x4096) -> PROJ
    gemm_tc<128, 0><<<dim3(32, 16, 1), 256, SM128>>>(
        S + OFF_H, S + OFF_WIN, in_b, S + OFF_PROJ, 4096, 1024, 1024, 1024, nullptr, 0);

    // 3. depthwise conv + SiLU -> x1c (plain) + x1cp (perm)
    conv_silu_k<<<dim3(Dv / 256, NROWS), 256>>>(
        S + OFF_PROJ, conv_w, conv_b, S + OFF_X1C, S + OFF_X1CP);

    // 4. dbc: (2048x2048)@(2048x160), split-K x4 + reduce
    gemm_tc<64, 3><<<dim3(3, 16, 4), 256, SM64>>>(
        S + OFF_X1CP, S + OFF_WDBC, nullptr, S + OFF_DBCP, 160, 512, 2048, 2048,
        nullptr, (size_t)NROWS * 160);
    reduce4_k<<<(NROWS * 160) / 256, 256>>>(S + OFF_DBCP, dbc_b, S + OFF_DBC);

    // 5. delta up-proj + softplus: (2048x128)@(128x2048)
    gemm_tc<128, 1><<<dim3(16, 16, 1), 256, SM128>>>(
        S + OFF_DBC, S + OFF_WDUP, dup_b, S + OFF_DELTA, 2048, 128, 160, 128, nullptr, 0);

    // 6. selective scan + silu(g) gating -> ymod (rounded, perm)
    scan_k<<<dim3(Dv / 16, 2), 256>>>(
        S + OFF_DBC, S + OFF_DELTA, S + OFF_X1C, S + OFF_PROJ, A_log, S + OFF_YMOD);

    // 7. out_proj + bias + residual -> d_out
    gemm_tc<64, 2><<<dim3(16, 16, 1), 256, SM64>>>(
        S + OFF_YMOD, S + OFF_WOUT, out_b, out, 1024, 2048, 2048, 2048, x, 0);
}

// round 10
// speedup vs baseline: 1.2022x; 1.2022x over previous
#include <cuda_runtime.h>
#include <cstdint>

// ---------------------------------------------------------------------------
// MambaBlock: B=2, T=1024, DM=1024, D=2048, N=16, K=4, DTR=128
// Round 10 (= round 8 resubmit; prior two benches died to container infra
// flake, not kernel faults): mma.sync tf32 GEMMs (tcgen05 unavailable —
// harness targets sm_103 without 'a'), 3-stage cp.async pipeline with a
// single __syncthreads per K-tile, split-K dbc, smem-staged selective scan.
// ---------------------------------------------------------------------------

#define DMv   1024
#define Dv    2048
#define Tv    1024
#define NROWS 2048
#define NSTv  16

// Scratch layout (floats)
#define OFF_H      0u          // 2048*1024
#define OFF_PROJ   2097152u    // 2048*4096
#define OFF_X1C    10485760u   // 2048*2048
#define OFF_DBC    14680064u   // 2048*160
#define OFF_DELTA  15007744u   // 2048*2048
#define OFF_YMOD   19202048u   // 2048*2048
#define OFF_DBCP   23396352u   // 4*2048*160
#define SCRATCH_FLOATS 24707072u

__device__ __align__(128) float g_scratch[SCRATCH_FLOATS];

__device__ __forceinline__ float silu_f(float v) {
    return v * (1.0f / (1.0f + __expf(-v)));
}
__device__ __forceinline__ unsigned f2tf32(float f) {
    unsigned u;
    asm("cvt.rna.tf32.f32 %0, %1;" : "=r"(u) : "f"(f));
    return u;
}
__device__ __forceinline__ void cp16(float* dst, const float* src, bool p) {
    unsigned d = (unsigned)__cvta_generic_to_shared(dst);
    int sz = p ? 16 : 0;
    asm volatile("cp.async.cg.shared.global [%0], [%1], 16, %2;\n"
                 :: "r"(d), "l"(src), "r"(sz));
}

// ---------------------------------------------------------------------------
// RMSNorm
// ---------------------------------------------------------------------------
__global__ void __launch_bounds__(256) rmsnorm_k(
    const float* __restrict__ x, const float* __restrict__ w, float* __restrict__ out)
{
    int row = blockIdx.x;
    const float4* xr = reinterpret_cast<const float4*>(x + (size_t)row * DMv);
    float4 v = xr[threadIdx.x];
    float s = v.x * v.x + v.y * v.y + v.z * v.z + v.w * v.w;
    #pragma unroll
    for (int o = 16; o; o >>= 1) s += __shfl_xor_sync(0xffffffffu, s, o);
    __shared__ float ws[8];
    if ((threadIdx.x & 31) == 0) ws[threadIdx.x >> 5] = s;
    __syncthreads();
    float tot = 0.f;
    #pragma unroll
    for (int i = 0; i < 8; i++) tot += ws[i];
    float scale = rsqrtf(tot * (1.0f / (float)DMv) + 1e-6f);
    float4 wv = reinterpret_cast<const float4*>(w)[threadIdx.x];
    float4 o;
    o.x = v.x * scale * wv.x; o.y = v.y * scale * wv.y;
    o.z = v.z * scale * wv.z; o.w = v.w * scale * wv.w;
    reinterpret_cast<float4*>(out + (size_t)row * DMv)[threadIdx.x] = o;
}

// ---------------------------------------------------------------------------
// 3-stage pipelined tf32 mma.sync GEMM. C[M,N] = A[M,K]@B[K,N] (+epilogue).
// BM=128, BK=32, BN in {64,128}. 256 thr = 8 warps 4(M)x2(N), warp 32 x BN/2.
// EPI 0: +bias  1: +bias,softplus  2: +bias,+res  3: raw (split-K partial)
// blockIdx.z = split-K part. Requires Kd % 32 == 0, Kd/32 >= 3.
// ---------------------------------------------------------------------------
template <int BN, int EPI>
__global__ void __launch_bounds__(256) gemm_tc(
    const float* __restrict__ A, const float* __restrict__ B,
    const float* __restrict__ bias, float* __restrict__ C,
    int N, int Kd, int lda, const float* __restrict__ res, size_t partStride)
{
    constexpr int BM = 128, BK = 32;
    constexpr int ASTR = BK + 8;            // A stored [m][k], padded
    constexpr int BSTR = BN + 8;            // B stored [k][n], padded
    constexpr int ASZ = BM * ASTR, BSZ = BK * BSTR, STAGE = ASZ + BSZ;
    constexpr int WNT = BN / 16;
    constexpr int NBI = (BK * BN / 4) / 256;

    extern __shared__ float smem[];

    int tid = threadIdx.x, lane = tid & 31, warp = tid >> 5;
    int wm = warp >> 1, wn = warp & 1;
    int bm = blockIdx.y * BM, bn = blockIdx.x * BN;
    int part = blockIdx.z;
    const float* Ap = A + (size_t)part * Kd;
    const float* Bp = B + (size_t)part * Kd * N;
    float* Cp = C + (size_t)part * partStride;

    float acc[2][WNT][4];
    #pragma unroll
    for (int i = 0; i < 2; i++)
        #pragma unroll
        for (int j = 0; j < WNT; j++)
            #pragma unroll
            for (int q = 0; q < 4; q++) acc[i][j][q] = 0.f;

    auto issue = [&](int st, int kt) {
        float* As = smem + st * STAGE;
        float* Bs = As + ASZ;
        #pragma unroll
        for (int i = 0; i < 4; i++) {
            int li = tid + i * 256;
            int m = li >> 3, c = (li & 7) * 4;
            cp16(As + m * ASTR + c, Ap + (size_t)(bm + m) * lda + kt + c, true);
        }
        #pragma unroll
        for (int i = 0; i < NBI; i++) {
            int li = tid + i * 256;
            int r, c4;
            if (BN == 128) { r = li >> 5; c4 = (li & 31) * 4; }
            else           { r = li >> 4; c4 = (li & 15) * 4; }
            cp16(Bs + r * BSTR + c4, Bp + (size_t)(kt + r) * N + bn + c4,
                 (bn + c4) < N);
        }
        asm volatile("cp.async.commit_group;\n" ::: "memory");
    };

    auto compute = [&](int st) {
        const float* As = smem + st * STAGE;
        const float* Bs = As + ASZ;
        #pragma unroll
        for (int ks = 0; ks < BK / 8; ks++) {
            int k0 = ks * 8;
            int kc = k0 + (lane & 3);
            unsigned af[2][4];
            #pragma unroll
            for (int mi = 0; mi < 2; mi++) {
                int mr = wm * 32 + mi * 16 + (lane >> 2);
                af[mi][0] = f2tf32(As[mr * ASTR + kc]);
                af[mi][1] = f2tf32(As[(mr + 8) * ASTR + kc]);
                af[mi][2] = f2tf32(As[mr * ASTR + kc + 4]);
                af[mi][3] = f2tf32(As[(mr + 8) * ASTR + kc + 4]);
            }
            #pragma unroll
            for (int ni = 0; ni < WNT; ni++) {
                int nc = wn * (BN / 2) + ni * 8 + (lane >> 2);
                unsigned b0 = f2tf32(Bs[kc * BSTR + nc]);
                unsigned b1 = f2tf32(Bs[(kc + 4) * BSTR + nc]);
                #pragma unroll
                for (int mi = 0; mi < 2; mi++) {
                    asm volatile(
                        "mma.sync.aligned.m16n8k8.row.col.f32.tf32.tf32.f32 "
                        "{%0,%1,%2,%3}, {%4,%5,%6,%7}, {%8,%9}, {%0,%1,%2,%3};\n"
                        : "+f"(acc[mi][ni][0]), "+f"(acc[mi][ni][1]),
                          "+f"(acc[mi][ni][2]), "+f"(acc[mi][ni][3])
                        : "r"(af[mi][0]), "r"(af[mi][1]), "r"(af[mi][2]), "r"(af[mi][3]),
                          "r"(b0), "r"(b1));
                }
            }
        }
    };

    int nt = Kd / BK;
    issue(0, 0);
    issue(1, BK);
    // 3-stage: at iter i, wait leaves <=1 group outstanding -> tile i ready.
    // The single sync also protects buffer (i+2)%3 == (i-1)%3 for refill.
    int st = 0;
    for (int i = 0; i < nt; i++) {
        if (i == nt - 1)
            asm volatile("cp.async.wait_group 0;\n" ::: "memory");
        else
            asm volatile("cp.async.wait_group 1;\n" ::: "memory");
        __syncthreads();
        if (i + 2 < nt) {
            int st2 = st + 2; if (st2 >= 3) st2 -= 3;
            issue(st2, (i + 2) * BK);
        }
        compute(st);
        if (++st == 3) st = 0;
    }

    // Epilogue
    #pragma unroll
    for (int mi = 0; mi < 2; mi++) {
        int r0 = bm + wm * 32 + mi * 16 + (lane >> 2);
        #pragma unroll
        for (int ni = 0; ni < WNT; ni++) {
            int c0 = bn + wn * (BN / 2) + ni * 8 + (lane & 3) * 2;
            if (c0 >= N) continue;
            #pragma unroll
            for (int h = 0; h < 2; h++) {
                int rr = r0 + h * 8;
                float v0 = acc[mi][ni][h * 2 + 0];
                float v1 = acc[mi][ni][h * 2 + 1];
                if (EPI != 3) { v0 += bias[c0]; v1 += bias[c0 + 1]; }
                if (EPI == 1) {
                    v0 = (v0 > 20.0f) ? v0 : log1pf(__expf(v0));
                    v1 = (v1 > 20.0f) ? v1 : log1pf(__expf(v1));
                }
                if (EPI == 2) {
                    float2 rv = *reinterpret_cast<const float2*>(&res[(size_t)rr * N + c0]);
                    v0 += rv.x; v1 += rv.y;
                }
                *reinterpret_cast<float2*>(&Cp[(size_t)rr * N + c0]) = make_float2(v0, v1);
            }
        }
    }
}

// ---------------------------------------------------------------------------
// Split-K reduce: dbc = sum of 4 partials + bias.
// ---------------------------------------------------------------------------
__global__ void __launch_bounds__(256) reduce4_k(
    const float* __restrict__ P, const float* __restrict__ bias, float* __restrict__ C)
{
    const size_t PS = (size_t)NROWS * 160;
    size_t i = (size_t)blockIdx.x * 256 + threadIdx.x;
    C[i] = P[i] + P[i + PS] + P[i + 2 * PS] + P[i + 3 * PS] + bias[i % 160];
}

// ---------------------------------------------------------------------------
// Depthwise causal conv (K=4) + SiLU
// ---------------------------------------------------------------------------
__global__ void __launch_bounds__(256) conv_silu_k(
    const float* __restrict__ proj, const float* __restrict__ cw,
    const float* __restrict__ cb, float* __restrict__ out)
{
    int d = blockIdx.x * 256 + threadIdx.x;
    int row = blockIdx.y;
    int t = row & (Tv - 1);
    int b = row >> 10;
    float4 w = *reinterpret_cast<const float4*>(cw + (size_t)d * 4);
    float acc = cb[d];
    const float* base = proj + (size_t)(b * Tv) * 4096 + d;
    if (t >= 3) acc = fmaf(base[(size_t)(t - 3) * 4096], w.x, acc);
    if (t >= 2) acc = fmaf(base[(size_t)(t - 2) * 4096], w.y, acc);
    if (t >= 1) acc = fmaf(base[(size_t)(t - 1) * 4096], w.z, acc);
    acc = fmaf(base[(size_t)t * 4096], w.w, acc);
    out[(size_t)row * Dv + d] = silu_f(acc);
}

// ---------------------------------------------------------------------------
// Selective scan, fully smem-staged. 256 thr = 16 channels x 16 states.
// Per 128-step chunk: stage B, C, delta, x coalesced into smem, then the
// sequential loop reads only smem (broadcast, conflict-free).
// ---------------------------------------------------------------------------
__global__ void __launch_bounds__(256) scan_k(
    const float* __restrict__ dbc, const float* __restrict__ delta,
    const float* __restrict__ x1c, const float* __restrict__ proj,
    const float* __restrict__ A_log, float* __restrict__ ymod)
{
    __shared__ float Bs[128][16];
    __shared__ float Cs[128][16];
    __shared__ float De[128][16];
    __shared__ float Xs[128][16];
    __shared__ float Ys[128][16];
    int tid = threadIdx.x;
    int n = tid & 15, grp = tid >> 4;
    int b = blockIdx.y;
    int d0 = blockIdx.x * 16;
    float An = -__expf(A_log[(size_t)(d0 + grp) * NSTv + n]);
    float h = 0.f;

    for (int c = 0; c < 8; c++) {
        __syncthreads();
        int t0 = c * 128;
        for (int idx = tid; idx < 2048; idx += 256) {
            int tl = idx >> 4, nn = idx & 15;
            size_t r = (size_t)(b * Tv + t0 + tl) * 160;
            Bs[tl][nn] = dbc[r + 128 + nn];
            Cs[tl][nn] = dbc[r + 144 + nn];
            size_t rr = (size_t)(b * Tv + t0 + tl) * Dv + d0 + nn;
            De[tl][nn] = delta[rr];
            Xs[tl][nn] = x1c[rr];
        }
        __syncthreads();
        #pragma unroll 8
        for (int tl = 0; tl < 128; tl++) {
            float de = De[tl][grp];
            float xx = Xs[tl][grp];
            float a = __expf(de * An);
            h = fmaf(a, h, de * Bs[tl][n] * xx);
            float p = h * Cs[tl][n];
            p += __shfl_xor_sync(0xffffffffu, p, 8);
            p += __shfl_xor_sync(0xffffffffu, p, 4);
            p += __shfl_xor_sync(0xffffffffu, p, 2);
            p += __shfl_xor_sync(0xffffffffu, p, 1);
            if (n == 0) Ys[tl][grp] = p;
        }
        __syncthreads();
        for (int idx = tid; idx < 2048; idx += 256) {
            int tl = idx >> 4, dl2 = idx & 15;
            int row = b * Tv + t0 + tl;
            float g = proj[(size_t)row * 4096 + 2048 + d0 + dl2];
            ymod[(size_t)row * Dv + d0 + dl2] = Ys[tl][dl2] * silu_f(g);
        }
    }
}

// ---------------------------------------------------------------------------
extern "C" void kernel_launch(void* const* d_in, const int* in_sizes, int n_in,
                              void* d_out, int out_size)
{
    const float* x      = (const float*)d_in[0];
    const float* rms_w  = (const float*)d_in[1];
    const float* in_W   = (const float*)d_in[2];
    const float* in_b   = (const float*)d_in[3];
    const float* conv_w = (const float*)d_in[4];
    const float* conv_b = (const float*)d_in[5];
    const float* A_log  = (const float*)d_in[6];
    const float* dbc_W  = (const float*)d_in[7];
    const float* dbc_b  = (const float*)d_in[8];
    const float* dup_W  = (const float*)d_in[9];
    const float* dup_b  = (const float*)d_in[10];
    const float* out_W  = (const float*)d_in[11];
    const float* out_b  = (const float*)d_in[12];
    float* out = (float*)d_out;

    float* S = nullptr;
    cudaGetSymbolAddress((void**)&S, g_scratch);

    // 3 stages: stage = 128*40 + 32*(BN+8) floats
    const int SM128 = 3 * (128 * 40 + 32 * 136) * 4;   // 113664 B
    const int SM64  = 3 * (128 * 40 + 32 * 72) * 4;    //  89088 B
    cudaFuncSetAttribute(gemm_tc<128, 0>, cudaFuncAttributeMaxDynamicSharedMemorySize, SM128);
    cudaFuncSetAttribute(gemm_tc<128, 1>, cudaFuncAttributeMaxDynamicSharedMemorySize, SM128);
    cudaFuncSetAttribute(gemm_tc<64, 2>,  cudaFuncAttributeMaxDynamicSharedMemorySize, SM64);
    cudaFuncSetAttribute(gemm_tc<64, 3>,  cudaFuncAttributeMaxDynamicSharedMemorySize, SM64);

    // 1. RMSNorm
    rmsnorm_k<<<NROWS, 256>>>(x, rms_w, S + OFF_H);

    // 2. in_proj: (2048x1024)@(1024x4096)
    gemm_tc<128, 0><<<dim3(32, 16, 1), 256, SM128>>>(
        S + OFF_H, in_W, in_b, S + OFF_PROJ, 4096, 1024, 1024, nullptr, 0);

    // 3. depthwise conv + SiLU
    conv_silu_k<<<dim3(Dv / 256, NROWS), 256>>>(S + OFF_PROJ, conv_w, conv_b, S + OFF_X1C);

    // 4. dbc: (2048x2048)@(2048x160), split-K x4 + reduce
    gemm_tc<64, 3><<<dim3(3, 16, 4), 256, SM64>>>(
        S + OFF_X1C, dbc_W, nullptr, S + OFF_DBCP, 160, 512, 2048, nullptr,
        (size_t)NROWS * 160);
    reduce4_k<<<(NROWS * 160) / 256, 256>>>(S + OFF_DBCP, dbc_b, S + OFF_DBC);

    // 5. delta up-proj + softplus: (2048x128)@(128x2048), A rows strided by 160
    gemm_tc<128, 1><<<dim3(16, 16, 1), 256, SM128>>>(
        S + OFF_DBC, dup_W, dup_b, S + OFF_DELTA, 2048, 128, 160, nullptr, 0);

    // 6. selective scan + silu(g) gating
    scan_k<<<dim3(Dv / 16, 2), 256>>>(
        S + OFF_DBC, S + OFF_DELTA, S + OFF_X1C, S + OFF_PROJ, A_log, S + OFF_YMOD);

    // 7. out_proj + bias + residual -> d_out
    gemm_tc<64, 2><<<dim3(16, 16, 1), 256, SM64>>>(
        S + OFF_YMOD, out_W, out_b, out, 1024, 2048, 2048, x, 0);
}

// round 11
// speedup vs baseline: 1.2241x; 1.0183x over previous
#include <cuda_runtime.h>
#include <cstdint>

// ---------------------------------------------------------------------------
// MambaBlock: B=2, T=1024, DM=1024, D=2048, N=16, K=4, DTR=128
// Round 11: round-10 base + occupancy fixes: A-tile pad 40->36 so BN=128
// 3-stage fits 2 CTAs/SM; dbc split-K x8.
// ---------------------------------------------------------------------------

#define DMv   1024
#define Dv    2048
#define Tv    1024
#define NROWS 2048
#define NSTv  16

// Scratch layout (floats)
#define OFF_H      0u          // 2048*1024
#define OFF_PROJ   2097152u    // 2048*4096
#define OFF_X1C    10485760u   // 2048*2048
#define OFF_DBC    14680064u   // 2048*160
#define OFF_DELTA  15007744u   // 2048*2048
#define OFF_YMOD   19202048u   // 2048*2048
#define OFF_DBCP   23396352u   // 8*2048*160 split-K partials
#define SCRATCH_FLOATS 26017792u

__device__ __align__(128) float g_scratch[SCRATCH_FLOATS];

__device__ __forceinline__ float silu_f(float v) {
    return v * (1.0f / (1.0f + __expf(-v)));
}
__device__ __forceinline__ unsigned f2tf32(float f) {
    unsigned u;
    asm("cvt.rna.tf32.f32 %0, %1;" : "=r"(u) : "f"(f));
    return u;
}
__device__ __forceinline__ void cp16(float* dst, const float* src, bool p) {
    unsigned d = (unsigned)__cvta_generic_to_shared(dst);
    int sz = p ? 16 : 0;
    asm volatile("cp.async.cg.shared.global [%0], [%1], 16, %2;\n"
                 :: "r"(d), "l"(src), "r"(sz));
}

// ---------------------------------------------------------------------------
// RMSNorm
// ---------------------------------------------------------------------------
__global__ void __launch_bounds__(256) rmsnorm_k(
    const float* __restrict__ x, const float* __restrict__ w, float* __restrict__ out)
{
    int row = blockIdx.x;
    const float4* xr = reinterpret_cast<const float4*>(x + (size_t)row * DMv);
    float4 v = xr[threadIdx.x];
    float s = v.x * v.x + v.y * v.y + v.z * v.z + v.w * v.w;
    #pragma unroll
    for (int o = 16; o; o >>= 1) s += __shfl_xor_sync(0xffffffffu, s, o);
    __shared__ float ws[8];
    if ((threadIdx.x & 31) == 0) ws[threadIdx.x >> 5] = s;
    __syncthreads();
    float tot = 0.f;
    #pragma unroll
    for (int i = 0; i < 8; i++) tot += ws[i];
    float scale = rsqrtf(tot * (1.0f / (float)DMv) + 1e-6f);
    float4 wv = reinterpret_cast<const float4*>(w)[threadIdx.x];
    float4 o;
    o.x = v.x * scale * wv.x; o.y = v.y * scale * wv.y;
    o.z = v.z * scale * wv.z; o.w = v.w * scale * wv.w;
    reinterpret_cast<float4*>(out + (size_t)row * DMv)[threadIdx.x] = o;
}

// ---------------------------------------------------------------------------
// 3-stage pipelined tf32 mma.sync GEMM. C[M,N] = A[M,K]@B[K,N] (+epilogue).
// BM=128, BK=32, BN in {64,128}. 256 thr = 8 warps 4(M)x2(N), warp 32 x BN/2.
// A pad 36 (conflict-free: banks (4m+k)%32 distinct), 2 CTAs/SM at BN=128.
// EPI 0: +bias  1: +bias,softplus  2: +bias,+res  3: raw (split-K partial)
// blockIdx.z = split-K part. Requires Kd % 32 == 0, Kd/32 >= 3.
// ---------------------------------------------------------------------------
template <int BN, int EPI>
__global__ void __launch_bounds__(256) gemm_tc(
    const float* __restrict__ A, const float* __restrict__ B,
    const float* __restrict__ bias, float* __restrict__ C,
    int N, int Kd, int lda, const float* __restrict__ res, size_t partStride)
{
    constexpr int BM = 128, BK = 32;
    constexpr int ASTR = BK + 4;            // 36: A stored [m][k]
    constexpr int BSTR = BN + 8;            // B stored [k][n]
    constexpr int ASZ = BM * ASTR, BSZ = BK * BSTR, STAGE = ASZ + BSZ;
    constexpr int WNT = BN / 16;
    constexpr int NBI = (BK * BN / 4) / 256;

    extern __shared__ float smem[];

    int tid = threadIdx.x, lane = tid & 31, warp = tid >> 5;
    int wm = warp >> 1, wn = warp & 1;
    int bm = blockIdx.y * BM, bn = blockIdx.x * BN;
    int part = blockIdx.z;
    const float* Ap = A + (size_t)part * Kd;
    const float* Bp = B + (size_t)part * Kd * N;
    float* Cp = C + (size_t)part * partStride;

    float acc[2][WNT][4];
    #pragma unroll
    for (int i = 0; i < 2; i++)
        #pragma unroll
        for (int j = 0; j < WNT; j++)
            #pragma unroll
            for (int q = 0; q < 4; q++) acc[i][j][q] = 0.f;

    auto issue = [&](int st, int kt) {
        float* As = smem + st * STAGE;
        float* Bs = As + ASZ;
        #pragma unroll
        for (int i = 0; i < 4; i++) {
            int li = tid + i * 256;
            int m = li >> 3, c = (li & 7) * 4;
            cp16(As + m * ASTR + c, Ap + (size_t)(bm + m) * lda + kt + c, true);
        }
        #pragma unroll
        for (int i = 0; i < NBI; i++) {
            int li = tid + i * 256;
            int r, c4;
            if (BN == 128) { r = li >> 5; c4 = (li & 31) * 4; }
            else           { r = li >> 4; c4 = (li & 15) * 4; }
            cp16(Bs + r * BSTR + c4, Bp + (size_t)(kt + r) * N + bn + c4,
                 (bn + c4) < N);
        }
        asm volatile("cp.async.commit_group;\n" ::: "memory");
    };

    auto compute = [&](int st) {
        const float* As = smem + st * STAGE;
        const float* Bs = As + ASZ;
        #pragma unroll
        for (int ks = 0; ks < BK / 8; ks++) {
            int k0 = ks * 8;
            int kc = k0 + (lane & 3);
            unsigned af[2][4];
            #pragma unroll
            for (int mi = 0; mi < 2; mi++) {
                int mr = wm * 32 + mi * 16 + (lane >> 2);
                af[mi][0] = f2tf32(As[mr * ASTR + kc]);
                af[mi][1] = f2tf32(As[(mr + 8) * ASTR + kc]);
                af[mi][2] = f2tf32(As[mr * ASTR + kc + 4]);
                af[mi][3] = f2tf32(As[(mr + 8) * ASTR + kc + 4]);
            }
            #pragma unroll
            for (int ni = 0; ni < WNT; ni++) {
                int nc = wn * (BN / 2) + ni * 8 + (lane >> 2);
                unsigned b0 = f2tf32(Bs[kc * BSTR + nc]);
                unsigned b1 = f2tf32(Bs[(kc + 4) * BSTR + nc]);
                #pragma unroll
                for (int mi = 0; mi < 2; mi++) {
                    asm volatile(
                        "mma.sync.aligned.m16n8k8.row.col.f32.tf32.tf32.f32 "
                        "{%0,%1,%2,%3}, {%4,%5,%6,%7}, {%8,%9}, {%0,%1,%2,%3};\n"
                        : "+f"(acc[mi][ni][0]), "+f"(acc[mi][ni][1]),
                          "+f"(acc[mi][ni][2]), "+f"(acc[mi][ni][3])
                        : "r"(af[mi][0]), "r"(af[mi][1]), "r"(af[mi][2]), "r"(af[mi][3]),
                          "r"(b0), "r"(b1));
                }
            }
        }
    };

    int nt = Kd / BK;
    issue(0, 0);
    issue(1, BK);
    int st = 0;
    for (int i = 0; i < nt; i++) {
        if (i == nt - 1)
            asm volatile("cp.async.wait_group 0;\n" ::: "memory");
        else
            asm volatile("cp.async.wait_group 1;\n" ::: "memory");
        __syncthreads();
        if (i + 2 < nt) {
            int st2 = st + 2; if (st2 >= 3) st2 -= 3;
            issue(st2, (i + 2) * BK);
        }
        compute(st);
        if (++st == 3) st = 0;
    }

    // Epilogue
    #pragma unroll
    for (int mi = 0; mi < 2; mi++) {
        int r0 = bm + wm * 32 + mi * 16 + (lane >> 2);
        #pragma unroll
        for (int ni = 0; ni < WNT; ni++) {
            int c0 = bn + wn * (BN / 2) + ni * 8 + (lane & 3) * 2;
            if (c0 >= N) continue;
            #pragma unroll
            for (int h = 0; h < 2; h++) {
                int rr = r0 + h * 8;
                float v0 = acc[mi][ni][h * 2 + 0];
                float v1 = acc[mi][ni][h * 2 + 1];
                if (EPI != 3) { v0 += bias[c0]; v1 += bias[c0 + 1]; }
                if (EPI == 1) {
                    v0 = (v0 > 20.0f) ? v0 : log1pf(__expf(v0));
                    v1 = (v1 > 20.0f) ? v1 : log1pf(__expf(v1));
                }
                if (EPI == 2) {
                    float2 rv = *reinterpret_cast<const float2*>(&res[(size_t)rr * N + c0]);
                    v0 += rv.x; v1 += rv.y;
                }
                *reinterpret_cast<float2*>(&Cp[(size_t)rr * N + c0]) = make_float2(v0, v1);
            }
        }
    }
}

// ---------------------------------------------------------------------------
// Split-K reduce: dbc = sum of 8 partials + bias.
// ---------------------------------------------------------------------------
__global__ void __launch_bounds__(256) reduce8_k(
    const float* __restrict__ P, const float* __restrict__ bias, float* __restrict__ C)
{
    const size_t PS = (size_t)NROWS * 160;
    size_t i = (size_t)blockIdx.x * 256 + threadIdx.x;
    float v = bias[i % 160];
    #pragma unroll
    for (int p = 0; p < 8; p++) v += P[i + p * PS];
    C[i] = v;
}

// ---------------------------------------------------------------------------
// Depthwise causal conv (K=4) + SiLU
// ---------------------------------------------------------------------------
__global__ void __launch_bounds__(256) conv_silu_k(
    const float* __restrict__ proj, const float* __restrict__ cw,
    const float* __restrict__ cb, float* __restrict__ out)
{
    int d = blockIdx.x * 256 + threadIdx.x;
    int row = blockIdx.y;
    int t = row & (Tv - 1);
    int b = row >> 10;
    float4 w = *reinterpret_cast<const float4*>(cw + (size_t)d * 4);
    float acc = cb[d];
    const float* base = proj + (size_t)(b * Tv) * 4096 + d;
    if (t >= 3) acc = fmaf(base[(size_t)(t - 3) * 4096], w.x, acc);
    if (t >= 2) acc = fmaf(base[(size_t)(t - 2) * 4096], w.y, acc);
    if (t >= 1) acc = fmaf(base[(size_t)(t - 1) * 4096], w.z, acc);
    acc = fmaf(base[(size_t)t * 4096], w.w, acc);
    out[(size_t)row * Dv + d] = silu_f(acc);
}

// ---------------------------------------------------------------------------
// Selective scan, fully smem-staged. 256 thr = 16 channels x 16 states.
// ---------------------------------------------------------------------------
__global__ void __launch_bounds__(256) scan_k(
    const float* __restrict__ dbc, const float* __restrict__ delta,
    const float* __restrict__ x1c, const float* __restrict__ proj,
    const float* __restrict__ A_log, float* __restrict__ ymod)
{
    __shared__ float Bs[128][16];
    __shared__ float Cs[128][16];
    __shared__ float De[128][16];
    __shared__ float Xs[128][16];
    __shared__ float Ys[128][16];
    int tid = threadIdx.x;
    int n = tid & 15, grp = tid >> 4;
    int b = blockIdx.y;
    int d0 = blockIdx.x * 16;
    float An = -__expf(A_log[(size_t)(d0 + grp) * NSTv + n]);
    float h = 0.f;

    for (int c = 0; c < 8; c++) {
        __syncthreads();
        int t0 = c * 128;
        for (int idx = tid; idx < 2048; idx += 256) {
            int tl = idx >> 4, nn = idx & 15;
            size_t r = (size_t)(b * Tv + t0 + tl) * 160;
            Bs[tl][nn] = dbc[r + 128 + nn];
            Cs[tl][nn] = dbc[r + 144 + nn];
            size_t rr = (size_t)(b * Tv + t0 + tl) * Dv + d0 + nn;
            De[tl][nn] = delta[rr];
            Xs[tl][nn] = x1c[rr];
        }
        __syncthreads();
        #pragma unroll 8
        for (int tl = 0; tl < 128; tl++) {
            float de = De[tl][grp];
            float xx = Xs[tl][grp];
            float a = __expf(de * An);
            h = fmaf(a, h, de * Bs[tl][n] * xx);
            float p = h * Cs[tl][n];
            p += __shfl_xor_sync(0xffffffffu, p, 8);
            p += __shfl_xor_sync(0xffffffffu, p, 4);
            p += __shfl_xor_sync(0xffffffffu, p, 2);
            p += __shfl_xor_sync(0xffffffffu, p, 1);
            if (n == 0) Ys[tl][grp] = p;
        }
        __syncthreads();
        for (int idx = tid; idx < 2048; idx += 256) {
            int tl = idx >> 4, dl2 = idx & 15;
            int row = b * Tv + t0 + tl;
            float g = proj[(size_t)row * 4096 + 2048 + d0 + dl2];
            ymod[(size_t)row * Dv + d0 + dl2] = Ys[tl][dl2] * silu_f(g);
        }
    }
}

// ---------------------------------------------------------------------------
extern "C" void kernel_launch(void* const* d_in, const int* in_sizes, int n_in,
                              void* d_out, int out_size)
{
    const float* x      = (const float*)d_in[0];
    const float* rms_w  = (const float*)d_in[1];
    const float* in_W   = (const float*)d_in[2];
    const float* in_b   = (const float*)d_in[3];
    const float* conv_w = (const float*)d_in[4];
    const float* conv_b = (const float*)d_in[5];
    const float* A_log  = (const float*)d_in[6];
    const float* dbc_W  = (const float*)d_in[7];
    const float* dbc_b  = (const float*)d_in[8];
    const float* dup_W  = (const float*)d_in[9];
    const float* dup_b  = (const float*)d_in[10];
    const float* out_W  = (const float*)d_in[11];
    const float* out_b  = (const float*)d_in[12];
    float* out = (float*)d_out;

    float* S = nullptr;
    cudaGetSymbolAddress((void**)&S, g_scratch);

    // 3 stages: stage = 128*36 + 32*(BN+8) floats
    const int SM128 = 3 * (128 * 36 + 32 * 136) * 4;   // 107520 B -> 2 CTAs/SM
    const int SM64  = 3 * (128 * 36 + 32 * 72) * 4;    //  82944 B -> 2 CTAs/SM
    cudaFuncSetAttribute(gemm_tc<128, 0>, cudaFuncAttributeMaxDynamicSharedMemorySize, SM128);
    cudaFuncSetAttribute(gemm_tc<128, 1>, cudaFuncAttributeMaxDynamicSharedMemorySize, SM128);
    cudaFuncSetAttribute(gemm_tc<64, 2>,  cudaFuncAttributeMaxDynamicSharedMemorySize, SM64);
    cudaFuncSetAttribute(gemm_tc<64, 3>,  cudaFuncAttributeMaxDynamicSharedMemorySize, SM64);

    // 1. RMSNorm
    rmsnorm_k<<<NROWS, 256>>>(x, rms_w, S + OFF_H);

    // 2. in_proj: (2048x1024)@(1024x4096)
    gemm_tc<128, 0><<<dim3(32, 16, 1), 256, SM128>>>(
        S + OFF_H, in_W, in_b, S + OFF_PROJ, 4096, 1024, 1024, nullptr, 0);

    // 3. depthwise conv + SiLU
    conv_silu_k<<<dim3(Dv / 256, NROWS), 256>>>(S + OFF_PROJ, conv_w, conv_b, S + OFF_X1C);

    // 4. dbc: (2048x2048)@(2048x160), split-K x8 + reduce
    gemm_tc<64, 3><<<dim3(3, 16, 8), 256, SM64>>>(
        S + OFF_X1C, dbc_W, nullptr, S + OFF_DBCP, 160, 256, 2048, nullptr,
        (size_t)NROWS * 160);
    reduce8_k<<<(NROWS * 160) / 256, 256>>>(S + OFF_DBCP, dbc_b, S + OFF_DBC);

    // 5. delta up-proj + softplus: (2048x128)@(128x2048), A rows strided by 160
    gemm_tc<128, 1><<<dim3(16, 16, 1), 256, SM128>>>(
        S + OFF_DBC, dup_W, dup_b, S + OFF_DELTA, 2048, 128, 160, nullptr, 0);

    // 6. selective scan + silu(g) gating
    scan_k<<<dim3(Dv / 16, 2), 256>>>(
        S + OFF_DBC, S + OFF_DELTA, S + OFF_X1C, S + OFF_PROJ, A_log, S + OFF_YMOD);

    // 7. out_proj + bias + residual -> d_out
    gemm_tc<64, 2><<<dim3(16, 16, 1), 256, SM64>>>(
        S + OFF_YMOD, out_W, out_b, out, 1024, 2048, 2048, x, 0);
}

// round 12
// speedup vs baseline: 1.3375x; 1.0926x over previous
#include <cuda_runtime.h>
#include <cstdint>

// ---------------------------------------------------------------------------
// MambaBlock: B=2, T=1024, DM=1024, D=2048, N=16, K=4, DTR=128
// Round 12: big-tile GEMM (256x128, warp tile 64x64 -> 33% MMA issue density)
// for in_proj / dup / out_proj(split-K x2); dbc split-K x8 on 128x64 kernel.
// ---------------------------------------------------------------------------

#define DMv   1024
#define Dv    2048
#define Tv    1024
#define NROWS 2048
#define NSTv  16

// Scratch layout (floats)
#define OFF_H      0u          // 2048*1024
#define OFF_PROJ   2097152u    // 2048*4096
#define OFF_X1C    10485760u   // 2048*2048
#define OFF_DBC    14680064u   // 2048*160
#define OFF_DELTA  15007744u   // 2048*2048
#define OFF_YMOD   19202048u   // 2048*2048
#define OFF_DBCP   23396352u   // 8*2048*160 split-K partials
#define OFF_OUTP   26017792u   // 2*2048*1024 out_proj split-K partials
#define SCRATCH_FLOATS 30212096u

__device__ __align__(128) float g_scratch[SCRATCH_FLOATS];

__device__ __forceinline__ float silu_f(float v) {
    return v * (1.0f / (1.0f + __expf(-v)));
}
__device__ __forceinline__ unsigned f2tf32(float f) {
    unsigned u;
    asm("cvt.rna.tf32.f32 %0, %1;" : "=r"(u) : "f"(f));
    return u;
}
__device__ __forceinline__ void cp16(float* dst, const float* src, bool p) {
    unsigned d = (unsigned)__cvta_generic_to_shared(dst);
    int sz = p ? 16 : 0;
    asm volatile("cp.async.cg.shared.global [%0], [%1], 16, %2;\n"
                 :: "r"(d), "l"(src), "r"(sz));
}

// ---------------------------------------------------------------------------
// RMSNorm
// ---------------------------------------------------------------------------
__global__ void __launch_bounds__(256) rmsnorm_k(
    const float* __restrict__ x, const float* __restrict__ w, float* __restrict__ out)
{
    int row = blockIdx.x;
    const float4* xr = reinterpret_cast<const float4*>(x + (size_t)row * DMv);
    float4 v = xr[threadIdx.x];
    float s = v.x * v.x + v.y * v.y + v.z * v.z + v.w * v.w;
    #pragma unroll
    for (int o = 16; o; o >>= 1) s += __shfl_xor_sync(0xffffffffu, s, o);
    __shared__ float ws[8];
    if ((threadIdx.x & 31) == 0) ws[threadIdx.x >> 5] = s;
    __syncthreads();
    float tot = 0.f;
    #pragma unroll
    for (int i = 0; i < 8; i++) tot += ws[i];
    float scale = rsqrtf(tot * (1.0f / (float)DMv) + 1e-6f);
    float4 wv = reinterpret_cast<const float4*>(w)[threadIdx.x];
    float4 o;
    o.x = v.x * scale * wv.x; o.y = v.y * scale * wv.y;
    o.z = v.z * scale * wv.z; o.w = v.w * scale * wv.w;
    reinterpret_cast<float4*>(out + (size_t)row * DMv)[threadIdx.x] = o;
}

// ---------------------------------------------------------------------------
// Big-tile 3-stage pipelined tf32 GEMM: BM=256, BN=128, BK=32.
// 256 thr = 8 warps as 4(M)x2(N); warp tile 64x64 (mi=4, ni=8).
// EPI 0: +bias  1: +bias,softplus  3: raw (split-K partial)
// blockIdx.z = split-K part. Requires M%256==0, N%128==0, Kd%32==0, Kd/32>=3.
// ---------------------------------------------------------------------------
template <int EPI>
__global__ void __launch_bounds__(256) gemm_big(
    const float* __restrict__ A, const float* __restrict__ B,
    const float* __restrict__ bias, float* __restrict__ C,
    int N, int Kd, int lda, size_t partStride)
{
    constexpr int BM = 256, BN = 128, BK = 32;
    constexpr int ASTR = BK + 4;            // 36
    constexpr int BSTR = BN + 8;            // 136
    constexpr int ASZ = BM * ASTR, BSZ = BK * BSTR, STAGE = ASZ + BSZ;

    extern __shared__ float smem[];

    int tid = threadIdx.x, lane = tid & 31, warp = tid >> 5;
    int wm = warp >> 1, wn = warp & 1;
    int bm = blockIdx.y * BM, bn = blockIdx.x * BN;
    int part = blockIdx.z;
    const float* Ap = A + (size_t)part * Kd;
    const float* Bp = B + (size_t)part * Kd * N;
    float* Cp = C + (size_t)part * partStride;

    float acc[4][8][4];
    #pragma unroll
    for (int i = 0; i < 4; i++)
        #pragma unroll
        for (int j = 0; j < 8; j++)
            #pragma unroll
            for (int q = 0; q < 4; q++) acc[i][j][q] = 0.f;

    auto issue = [&](int st, int kt) {
        float* As = smem + st * STAGE;
        float* Bs = As + ASZ;
        #pragma unroll
        for (int i = 0; i < 8; i++) {
            int li = tid + i * 256;
            int m = li >> 3, c = (li & 7) * 4;
            cp16(As + m * ASTR + c, Ap + (size_t)(bm + m) * lda + kt + c, true);
        }
        #pragma unroll
        for (int i = 0; i < 4; i++) {
            int li = tid + i * 256;
            int r = li >> 5, c4 = (li & 31) * 4;
            cp16(Bs + r * BSTR + c4, Bp + (size_t)(kt + r) * N + bn + c4, true);
        }
        asm volatile("cp.async.commit_group;\n" ::: "memory");
    };

    auto compute = [&](int st) {
        const float* As = smem + st * STAGE;
        const float* Bs = As + ASZ;
        #pragma unroll
        for (int ks = 0; ks < BK / 8; ks++) {
            int kc = ks * 8 + (lane & 3);
            unsigned af[4][4];
            #pragma unroll
            for (int mi = 0; mi < 4; mi++) {
                int mr = wm * 64 + mi * 16 + (lane >> 2);
                af[mi][0] = f2tf32(As[mr * ASTR + kc]);
                af[mi][1] = f2tf32(As[(mr + 8) * ASTR + kc]);
                af[mi][2] = f2tf32(As[mr * ASTR + kc + 4]);
                af[mi][3] = f2tf32(As[(mr + 8) * ASTR + kc + 4]);
            }
            #pragma unroll
            for (int ni = 0; ni < 8; ni++) {
                int nc = wn * 64 + ni * 8 + (lane >> 2);
                unsigned b0 = f2tf32(Bs[kc * BSTR + nc]);
                unsigned b1 = f2tf32(Bs[(kc + 4) * BSTR + nc]);
                #pragma unroll
                for (int mi = 0; mi < 4; mi++) {
                    asm volatile(
                        "mma.sync.aligned.m16n8k8.row.col.f32.tf32.tf32.f32 "
                        "{%0,%1,%2,%3}, {%4,%5,%6,%7}, {%8,%9}, {%0,%1,%2,%3};\n"
                        : "+f"(acc[mi][ni][0]), "+f"(acc[mi][ni][1]),
                          "+f"(acc[mi][ni][2]), "+f"(acc[mi][ni][3])
                        : "r"(af[mi][0]), "r"(af[mi][1]), "r"(af[mi][2]), "r"(af[mi][3]),
                          "r"(b0), "r"(b1));
                }
            }
        }
    };

    int nt = Kd / BK;
    issue(0, 0);
    issue(1, BK);
    int st = 0;
    for (int i = 0; i < nt; i++) {
        if (i == nt - 1)
            asm volatile("cp.async.wait_group 0;\n" ::: "memory");
        else
            asm volatile("cp.async.wait_group 1;\n" ::: "memory");
        __syncthreads();
        if (i + 2 < nt) {
            int st2 = st + 2; if (st2 >= 3) st2 -= 3;
            issue(st2, (i + 2) * BK);
        }
        compute(st);
        if (++st == 3) st = 0;
    }

    // Epilogue
    #pragma unroll
    for (int mi = 0; mi < 4; mi++) {
        int r0 = bm + wm * 64 + mi * 16 + (lane >> 2);
        #pragma unroll
        for (int ni = 0; ni < 8; ni++) {
            int c0 = bn + wn * 64 + ni * 8 + (lane & 3) * 2;
            #pragma unroll
            for (int h = 0; h < 2; h++) {
                int rr = r0 + h * 8;
                float v0 = acc[mi][ni][h * 2 + 0];
                float v1 = acc[mi][ni][h * 2 + 1];
                if (EPI != 3) { v0 += bias[c0]; v1 += bias[c0 + 1]; }
                if (EPI == 1) {
                    v0 = (v0 > 20.0f) ? v0 : log1pf(__expf(v0));
                    v1 = (v1 > 20.0f) ? v1 : log1pf(__expf(v1));
                }
                *reinterpret_cast<float2*>(&Cp[(size_t)rr * N + c0]) = make_float2(v0, v1);
            }
        }
    }
}

// ---------------------------------------------------------------------------
// 128x64 3-stage pipelined GEMM (dbc split-K partials). EPI=3 semantics.
// ---------------------------------------------------------------------------
__global__ void __launch_bounds__(256) gemm_dbc(
    const float* __restrict__ A, const float* __restrict__ B,
    float* __restrict__ C, int N, int Kd, int lda, size_t partStride)
{
    constexpr int BM = 128, BK = 32, BN = 64;
    constexpr int ASTR = BK + 4, BSTR = BN + 8;
    constexpr int ASZ = BM * ASTR, BSZ = BK * BSTR, STAGE = ASZ + BSZ;

    extern __shared__ float smem[];

    int tid = threadIdx.x, lane = tid & 31, warp = tid >> 5;
    int wm = warp >> 1, wn = warp & 1;
    int bm = blockIdx.y * BM, bn = blockIdx.x * BN;
    int part = blockIdx.z;
    const float* Ap = A + (size_t)part * Kd;
    const float* Bp = B + (size_t)part * Kd * N;
    float* Cp = C + (size_t)part * partStride;

    float acc[2][4][4];
    #pragma unroll
    for (int i = 0; i < 2; i++)
        #pragma unroll
        for (int j = 0; j < 4; j++)
            #pragma unroll
            for (int q = 0; q < 4; q++) acc[i][j][q] = 0.f;

    auto issue = [&](int st, int kt) {
        float* As = smem + st * STAGE;
        float* Bs = As + ASZ;
        #pragma unroll
        for (int i = 0; i < 4; i++) {
            int li = tid + i * 256;
            int m = li >> 3, c = (li & 7) * 4;
            cp16(As + m * ASTR + c, Ap + (size_t)(bm + m) * lda + kt + c, true);
        }
        #pragma unroll
        for (int i = 0; i < 2; i++) {
            int li = tid + i * 256;
            int r = li >> 4, c4 = (li & 15) * 4;
            cp16(Bs + r * BSTR + c4, Bp + (size_t)(kt + r) * N + bn + c4,
                 (bn + c4) < N);
        }
        asm volatile("cp.async.commit_group;\n" ::: "memory");
    };

    auto compute = [&](int st) {
        const float* As = smem + st * STAGE;
        const float* Bs = As + ASZ;
        #pragma unroll
        for (int ks = 0; ks < BK / 8; ks++) {
            int kc = ks * 8 + (lane & 3);
            unsigned af[2][4];
            #pragma unroll
            for (int mi = 0; mi < 2; mi++) {
                int mr = wm * 32 + mi * 16 + (lane >> 2);
                af[mi][0] = f2tf32(As[mr * ASTR + kc]);
                af[mi][1] = f2tf32(As[(mr + 8) * ASTR + kc]);
                af[mi][2] = f2tf32(As[mr * ASTR + kc + 4]);
                af[mi][3] = f2tf32(As[(mr + 8) * ASTR + kc + 4]);
            }
            #pragma unroll
            for (int ni = 0; ni < 4; ni++) {
                int nc = wn * 32 + ni * 8 + (lane >> 2);
                unsigned b0 = f2tf32(Bs[kc * BSTR + nc]);
                unsigned b1 = f2tf32(Bs[(kc + 4) * BSTR + nc]);
                #pragma unroll
                for (int mi = 0; mi < 2; mi++) {
                    asm volatile(
                        "mma.sync.aligned.m16n8k8.row.col.f32.tf32.tf32.f32 "
                        "{%0,%1,%2,%3}, {%4,%5,%6,%7}, {%8,%9}, {%0,%1,%2,%3};\n"
                        : "+f"(acc[mi][ni][0]), "+f"(acc[mi][ni][1]),
                          "+f"(acc[mi][ni][2]), "+f"(acc[mi][ni][3])
                        : "r"(af[mi][0]), "r"(af[mi][1]), "r"(af[mi][2]), "r"(af[mi][3]),
                          "r"(b0), "r"(b1));
                }
            }
        }
    };

    int nt = Kd / BK;
    issue(0, 0);
    issue(1, BK);
    int st = 0;
    for (int i = 0; i < nt; i++) {
        if (i == nt - 1)
            asm volatile("cp.async.wait_group 0;\n" ::: "memory");
        else
            asm volatile("cp.async.wait_group 1;\n" ::: "memory");
        __syncthreads();
        if (i + 2 < nt) {
            int st2 = st + 2; if (st2 >= 3) st2 -= 3;
            issue(st2, (i + 2) * BK);
        }
        compute(st);
        if (++st == 3) st = 0;
    }

    #pragma unroll
    for (int mi = 0; mi < 2; mi++) {
        int r0 = bm + wm * 32 + mi * 16 + (lane >> 2);
        #pragma unroll
        for (int ni = 0; ni < 4; ni++) {
            int c0 = bn + wn * 32 + ni * 8 + (lane & 3) * 2;
            if (c0 >= N) continue;
            #pragma unroll
            for (int h = 0; h < 2; h++) {
                int rr = r0 + h * 8;
                *reinterpret_cast<float2*>(&Cp[(size_t)rr * N + c0]) =
                    make_float2(acc[mi][ni][h * 2 + 0], acc[mi][ni][h * 2 + 1]);
            }
        }
    }
}

// ---------------------------------------------------------------------------
// Reduces
// ---------------------------------------------------------------------------
__global__ void __launch_bounds__(256) reduce8_k(
    const float* __restrict__ P, const float* __restrict__ bias, float* __restrict__ C)
{
    const size_t PS = (size_t)NROWS * 160;
    size_t i = (size_t)blockIdx.x * 256 + threadIdx.x;
    float v = bias[i % 160];
    #pragma unroll
    for (int p = 0; p < 8; p++) v += P[i + p * PS];
    C[i] = v;
}

// out = P0 + P1 + bias + residual
__global__ void __launch_bounds__(256) reduce2_out_k(
    const float* __restrict__ P, const float* __restrict__ bias,
    const float* __restrict__ x, float* __restrict__ C)
{
    const size_t PS = (size_t)NROWS * DMv;
    size_t i = ((size_t)blockIdx.x * 256 + threadIdx.x) * 4;
    float4 a = *reinterpret_cast<const float4*>(&P[i]);
    float4 b = *reinterpret_cast<const float4*>(&P[i + PS]);
    float4 r = *reinterpret_cast<const float4*>(&x[i]);
    const float4 bv = *reinterpret_cast<const float4*>(&bias[i % DMv]);
    float4 o;
    o.x = a.x + b.x + r.x + bv.x; o.y = a.y + b.y + r.y + bv.y;
    o.z = a.z + b.z + r.z + bv.z; o.w = a.w + b.w + r.w + bv.w;
    *reinterpret_cast<float4*>(&C[i]) = o;
}

// ---------------------------------------------------------------------------
// Depthwise causal conv (K=4) + SiLU
// ---------------------------------------------------------------------------
__global__ void __launch_bounds__(256) conv_silu_k(
    const float* __restrict__ proj, const float* __restrict__ cw,
    const float* __restrict__ cb, float* __restrict__ out)
{
    int d = blockIdx.x * 256 + threadIdx.x;
    int row = blockIdx.y;
    int t = row & (Tv - 1);
    int b = row >> 10;
    float4 w = *reinterpret_cast<const float4*>(cw + (size_t)d * 4);
    float acc = cb[d];
    const float* base = proj + (size_t)(b * Tv) * 4096 + d;
    if (t >= 3) acc = fmaf(base[(size_t)(t - 3) * 4096], w.x, acc);
    if (t >= 2) acc = fmaf(base[(size_t)(t - 2) * 4096], w.y, acc);
    if (t >= 1) acc = fmaf(base[(size_t)(t - 1) * 4096], w.z, acc);
    acc = fmaf(base[(size_t)t * 4096], w.w, acc);
    out[(size_t)row * Dv + d] = silu_f(acc);
}

// ---------------------------------------------------------------------------
// Selective scan, smem-staged. 256 thr = 16 channels x 16 states.
// ---------------------------------------------------------------------------
__global__ void __launch_bounds__(256) scan_k(
    const float* __restrict__ dbc, const float* __restrict__ delta,
    const float* __restrict__ x1c, const float* __restrict__ proj,
    const float* __restrict__ A_log, float* __restrict__ ymod)
{
    __shared__ float Bs[128][16];
    __shared__ float Cs[128][16];
    __shared__ float De[128][16];
    __shared__ float Xs[128][16];
    __shared__ float Ys[128][16];
    int tid = threadIdx.x;
    int n = tid & 15, grp = tid >> 4;
    int b = blockIdx.y;
    int d0 = blockIdx.x * 16;
    float An = -__expf(A_log[(size_t)(d0 + grp) * NSTv + n]);
    float h = 0.f;

    for (int c = 0; c < 8; c++) {
        __syncthreads();
        int t0 = c * 128;
        for (int idx = tid; idx < 2048; idx += 256) {
            int tl = idx >> 4, nn = idx & 15;
            size_t r = (size_t)(b * Tv + t0 + tl) * 160;
            Bs[tl][nn] = dbc[r + 128 + nn];
            Cs[tl][nn] = dbc[r + 144 + nn];
            size_t rr = (size_t)(b * Tv + t0 + tl) * Dv + d0 + nn;
            De[tl][nn] = delta[rr];
            Xs[tl][nn] = x1c[rr];
        }
        __syncthreads();
        #pragma unroll 8
        for (int tl = 0; tl < 128; tl++) {
            float de = De[tl][grp];
            float xx = Xs[tl][grp];
            float a = __expf(de * An);
            h = fmaf(a, h, de * Bs[tl][n] * xx);
            float p = h * Cs[tl][n];
            p += __shfl_xor_sync(0xffffffffu, p, 8);
            p += __shfl_xor_sync(0xffffffffu, p, 4);
            p += __shfl_xor_sync(0xffffffffu, p, 2);
            p += __shfl_xor_sync(0xffffffffu, p, 1);
            if (n == 0) Ys[tl][grp] = p;
        }
        __syncthreads();
        for (int idx = tid; idx < 2048; idx += 256) {
            int tl = idx >> 4, dl2 = idx & 15;
            int row = b * Tv + t0 + tl;
            float g = proj[(size_t)row * 4096 + 2048 + d0 + dl2];
            ymod[(size_t)row * Dv + d0 + dl2] = Ys[tl][dl2] * silu_f(g);
        }
    }
}

// ---------------------------------------------------------------------------
extern "C" void kernel_launch(void* const* d_in, const int* in_sizes, int n_in,
                              void* d_out, int out_size)
{
    const float* x      = (const float*)d_in[0];
    const float* rms_w  = (const float*)d_in[1];
    const float* in_W   = (const float*)d_in[2];
    const float* in_b   = (const float*)d_in[3];
    const float* conv_w = (const float*)d_in[4];
    const float* conv_b = (const float*)d_in[5];
    const float* A_log  = (const float*)d_in[6];
    const float* dbc_W  = (const float*)d_in[7];
    const float* dbc_b  = (const float*)d_in[8];
    const float* dup_W  = (const float*)d_in[9];
    const float* dup_b  = (const float*)d_in[10];
    const float* out_W  = (const float*)d_in[11];
    const float* out_b  = (const float*)d_in[12];
    float* out = (float*)d_out;

    float* S = nullptr;
    cudaGetSymbolAddress((void**)&S, g_scratch);

    const int SMBIG = 3 * (256 * 36 + 32 * 136) * 4;   // 162816 B
    const int SMDBC = 3 * (128 * 36 + 32 * 72) * 4;    //  82944 B
    cudaFuncSetAttribute(gemm_big<0>, cudaFuncAttributeMaxDynamicSharedMemorySize, SMBIG);
    cudaFuncSetAttribute(gemm_big<1>, cudaFuncAttributeMaxDynamicSharedMemorySize, SMBIG);
    cudaFuncSetAttribute(gemm_big<3>, cudaFuncAttributeMaxDynamicSharedMemorySize, SMBIG);
    cudaFuncSetAttribute(gemm_dbc,    cudaFuncAttributeMaxDynamicSharedMemorySize, SMDBC);

    // 1. RMSNorm
    rmsnorm_k<<<NROWS, 256>>>(x, rms_w, S + OFF_H);

    // 2. in_proj: (2048x1024)@(1024x4096)   grid 32x8 = 256 CTAs
    gemm_big<0><<<dim3(32, 8, 1), 256, SMBIG>>>(
        S + OFF_H, in_W, in_b, S + OFF_PROJ, 4096, 1024, 1024, 0);

    // 3. depthwise conv + SiLU
    conv_silu_k<<<dim3(Dv / 256, NROWS), 256>>>(S + OFF_PROJ, conv_w, conv_b, S + OFF_X1C);

    // 4. dbc: (2048x2048)@(2048x160), split-K x8 + reduce
    gemm_dbc<<<dim3(3, 16, 8), 256, SMDBC>>>(
        S + OFF_X1C, dbc_W, S + OFF_DBCP, 160, 256, 2048, (size_t)NROWS * 160);
    reduce8_k<<<(NROWS * 160) / 256, 256>>>(S + OFF_DBCP, dbc_b, S + OFF_DBC);

    // 5. delta up-proj + softplus: (2048x128)@(128x2048)   grid 16x8 = 128
    gemm_big<1><<<dim3(16, 8, 1), 256, SMBIG>>>(
        S + OFF_DBC, dup_W, dup_b, S + OFF_DELTA, 2048, 128, 160, 0);

    // 6. selective scan + silu(g) gating
    scan_k<<<dim3(Dv / 16, 2), 256>>>(
        S + OFF_DBC, S + OFF_DELTA, S + OFF_X1C, S + OFF_PROJ, A_log, S + OFF_YMOD);

    // 7. out_proj split-K x2: (2048x2048)@(2048x1024)   grid 8x8x2 = 128
    gemm_big<3><<<dim3(8, 8, 2), 256, SMBIG>>>(
        S + OFF_YMOD, out_W, nullptr, S + OFF_OUTP, 1024, 1024, 2048,
        (size_t)NROWS * DMv);
    reduce2_out_k<<<(NROWS * DMv) / 1024, 256>>>(S + OFF_OUTP, out_b, x, out);
}